// round 4
// baseline (speedup 1.0000x reference)
#include <cuda_runtime.h>
#include <cuda_bf16.h>

// Cosine similarity per row: out[i] = dot(q_i, d_i) / (||q_i|| * ||d_i||)
// N = 262144 rows, D = 256 fp32.
// Persistent kernel: grid-stride over rows, one warp per row, 2 rows per
// loop iteration with all 8 float4 loads front-batched (MLP_p1 = 8).
// Streaming cache hints (__ldcs) since data is touched exactly once.

#define D_DIM 256
#define D4 (D_DIM / 4)
#define THREADS_PER_BLOCK 256
#define WARPS_PER_BLOCK (THREADS_PER_BLOCK / 32)
#define GRID_BLOCKS (148 * 8)

__device__ __forceinline__ void row_sums(const float4& qa, const float4& qb,
                                         const float4& da, const float4& db,
                                         float& dot, float& qq, float& dd) {
    dot = qa.x * da.x + qa.y * da.y + qa.z * da.z + qa.w * da.w
        + qb.x * db.x + qb.y * db.y + qb.z * db.z + qb.w * db.w;
    qq  = qa.x * qa.x + qa.y * qa.y + qa.z * qa.z + qa.w * qa.w
        + qb.x * qb.x + qb.y * qb.y + qb.z * qb.z + qb.w * qb.w;
    dd  = da.x * da.x + da.y * da.y + da.z * da.z + da.w * da.w
        + db.x * db.x + db.y * db.y + db.z * db.z + db.w * db.w;
}

__global__ __launch_bounds__(THREADS_PER_BLOCK)
void cosine_sim_kernel(const float4* __restrict__ q4,
                       const float4* __restrict__ d4,
                       float* __restrict__ out,
                       int n_rows) {
    const int lane = threadIdx.x & 31;
    const int gwarp = (blockIdx.x * THREADS_PER_BLOCK + threadIdx.x) >> 5;
    const int nwarps = (gridDim.x * THREADS_PER_BLOCK) >> 5;

    int row = gwarp;

    // Main loop: two rows per iteration, all 8 loads issued before any math.
    for (; row + nwarps < n_rows; row += 2 * nwarps) {
        const int r0 = row;
        const int r1 = row + nwarps;
        const float4* q0 = q4 + (size_t)r0 * D4;
        const float4* d0 = d4 + (size_t)r0 * D4;
        const float4* q1 = q4 + (size_t)r1 * D4;
        const float4* d1 = d4 + (size_t)r1 * D4;

        float4 qa0 = __ldcs(q0 + lane);
        float4 qb0 = __ldcs(q0 + lane + 32);
        float4 da0 = __ldcs(d0 + lane);
        float4 db0 = __ldcs(d0 + lane + 32);
        float4 qa1 = __ldcs(q1 + lane);
        float4 qb1 = __ldcs(q1 + lane + 32);
        float4 da1 = __ldcs(d1 + lane);
        float4 db1 = __ldcs(d1 + lane + 32);

        float dot0, qq0, dd0, dot1, qq1, dd1;
        row_sums(qa0, qb0, da0, db0, dot0, qq0, dd0);
        row_sums(qa1, qb1, da1, db1, dot1, qq1, dd1);

        // Two independent butterfly chains — interleaved for ILP.
        #pragma unroll
        for (int off = 16; off > 0; off >>= 1) {
            dot0 += __shfl_xor_sync(0xFFFFFFFFu, dot0, off);
            dot1 += __shfl_xor_sync(0xFFFFFFFFu, dot1, off);
            qq0  += __shfl_xor_sync(0xFFFFFFFFu, qq0,  off);
            qq1  += __shfl_xor_sync(0xFFFFFFFFu, qq1,  off);
            dd0  += __shfl_xor_sync(0xFFFFFFFFu, dd0,  off);
            dd1  += __shfl_xor_sync(0xFFFFFFFFu, dd1,  off);
        }

        if (lane == 0) {
            __stcs(out + r0, dot0 * rsqrtf(qq0 * dd0));
            __stcs(out + r1, dot1 * rsqrtf(qq1 * dd1));
        }
    }

    // Tail: at most one remaining row for this warp.
    if (row < n_rows) {
        const float4* q0 = q4 + (size_t)row * D4;
        const float4* d0 = d4 + (size_t)row * D4;

        float4 qa = __ldcs(q0 + lane);
        float4 qb = __ldcs(q0 + lane + 32);
        float4 da = __ldcs(d0 + lane);
        float4 db = __ldcs(d0 + lane + 32);

        float dot, qq, dd;
        row_sums(qa, qb, da, db, dot, qq, dd);

        #pragma unroll
        for (int off = 16; off > 0; off >>= 1) {
            dot += __shfl_xor_sync(0xFFFFFFFFu, dot, off);
            qq  += __shfl_xor_sync(0xFFFFFFFFu, qq,  off);
            dd  += __shfl_xor_sync(0xFFFFFFFFu, dd,  off);
        }

        if (lane == 0) {
            __stcs(out + row, dot * rsqrtf(qq * dd));
        }
    }
}

extern "C" void kernel_launch(void* const* d_in, const int* in_sizes, int n_in,
                              void* d_out, int out_size) {
    const float4* q = (const float4*)d_in[0];
    const float4* d = (const float4*)d_in[1];
    float* out = (float*)d_out;

    const int n_rows = in_sizes[0] / D_DIM;

    cosine_sim_kernel<<<GRID_BLOCKS, THREADS_PER_BLOCK>>>(q, d, out, n_rows);
}

// round 5
// speedup vs baseline: 1.0731x; 1.0731x over previous
#include <cuda_runtime.h>
#include <cuda_bf16.h>

// Cosine similarity per row: out[i] = dot(q_i, d_i) / (||q_i|| * ||d_i||)
// N = 262144 rows, D = 256 fp32. One warp per row; each lane handles 8
// elements via two float4 loads per input tensor. Streaming (evict-first)
// cache hints since every byte is touched exactly once.

#define D_DIM 256
#define D4 (D_DIM / 4)
#define THREADS_PER_BLOCK 256
#define WARPS_PER_BLOCK (THREADS_PER_BLOCK / 32)

__global__ __launch_bounds__(THREADS_PER_BLOCK, 8)
void cosine_sim_kernel(const float4* __restrict__ q4,
                       const float4* __restrict__ d4,
                       float* __restrict__ out,
                       int n_rows) {
    const int warp_id = (blockIdx.x * WARPS_PER_BLOCK) + (threadIdx.x >> 5);
    const int lane = threadIdx.x & 31;
    if (warp_id >= n_rows) return;

    const float4* qr = q4 + (size_t)warp_id * D4;
    const float4* dr = d4 + (size_t)warp_id * D4;

    // Front-batch all 4 LDG.128, interleaving the q and d streams.
    float4 qa = __ldcs(qr + lane);
    float4 da = __ldcs(dr + lane);
    float4 qb = __ldcs(qr + lane + 32);
    float4 db = __ldcs(dr + lane + 32);

    float dot = qa.x * da.x + qa.y * da.y + qa.z * da.z + qa.w * da.w
              + qb.x * db.x + qb.y * db.y + qb.z * db.z + qb.w * db.w;
    float qq  = qa.x * qa.x + qa.y * qa.y + qa.z * qa.z + qa.w * qa.w
              + qb.x * qb.x + qb.y * qb.y + qb.z * qb.z + qb.w * qb.w;
    float dd  = da.x * da.x + da.y * da.y + da.z * da.z + da.w * da.w
              + db.x * db.x + db.y * db.y + db.z * db.z + db.w * db.w;

    // Warp butterfly reduction of the three partial sums.
    #pragma unroll
    for (int off = 16; off > 0; off >>= 1) {
        dot += __shfl_xor_sync(0xFFFFFFFFu, dot, off);
        qq  += __shfl_xor_sync(0xFFFFFFFFu, qq,  off);
        dd  += __shfl_xor_sync(0xFFFFFFFFu, dd,  off);
    }

    if (lane == 0) {
        __stcs(out + warp_id, dot * rsqrtf(qq * dd));
    }
}

extern "C" void kernel_launch(void* const* d_in, const int* in_sizes, int n_in,
                              void* d_out, int out_size) {
    const float4* q = (const float4*)d_in[0];
    const float4* d = (const float4*)d_in[1];
    float* out = (float*)d_out;

    const int n_rows = in_sizes[0] / D_DIM;
    const int blocks = (n_rows + WARPS_PER_BLOCK - 1) / WARPS_PER_BLOCK;

    cosine_sim_kernel<<<blocks, THREADS_PER_BLOCK>>>(q, d, out, n_rows);
}